// round 15
// baseline (speedup 1.0000x reference)
#include <cuda_runtime.h>
#include <math.h>
#include <stdint.h>

#define BB 8
#define SS 4096
#define HH 4096
#define DD 128
#define NMAX 64
#define NT 64            /* k-slices (h tiles of 64) */
#define HT 64
#define TPB 128
#define MROWS 48         /* MMA-covered rows (3 m-tiles of 16) */
#define AS 68            /* padded A row stride (floats) */
#define ARR_TARGET NT

// -------- persistent scratch: zero at load; tail re-zeros each replay ------
__device__ float g_K[BB][NMAX][DD];
__device__ float g_Q[BB][DD];
__device__ float g_V[BB][NMAX];
__device__ float g_rew[BB];
__device__ int   g_arrive[BB];
__device__ int   g_done;

__device__ __forceinline__ void red_f32(float* p, float v) {
    asm volatile("red.global.add.f32 [%0], %1;" :: "l"(p), "f"(v) : "memory");
}
__device__ __forceinline__ void red_v2(float* p, float x, float y) {
    asm volatile("red.global.add.v2.f32 [%0], {%1,%2};"
                 :: "l"(p), "f"(x), "f"(y) : "memory");
}
__device__ __forceinline__ uint32_t f2tf(float f) {
    uint32_t u; asm("cvt.rna.tf32.f32 %0,%1;" : "=r"(u) : "f"(f)); return u;
}

#define MMA(c0,c1,c2,c3,a0,a1,a2,a3,b0,b1)                                 \
    asm volatile("mma.sync.aligned.m16n8k8.row.col.f32.tf32.tf32.f32 "     \
        "{%0,%1,%2,%3},{%4,%5,%6,%7},{%8,%9},{%0,%1,%2,%3};"               \
        : "+f"(c0), "+f"(c1), "+f"(c2), "+f"(c3)                           \
        : "r"(a0), "r"(a1), "r"(a2), "r"(a3), "r"(b0), "r"(b1))

// ---------------------------------------------------------------------------
// ONE fused kernel. grid=(NT, BB), 128 threads (4 warps).
// R14 structure + ILP surgery: B fragments software-pipelined across kt
// (kt=0 issued at kernel top), Q projection with 4 accumulator chains.
// ---------------------------------------------------------------------------
__global__ void __launch_bounds__(TPB)
k_fused(const float* __restrict__ hid,
        const int*   __restrict__ mask,
        const float* __restrict__ Wq,
        const float* __restrict__ bq,
        const float* __restrict__ Wk,
        const float* __restrict__ bk,
        const float* __restrict__ Wr,
        const float* __restrict__ br,
        float* __restrict__ out, int out_size) {
    const int b    = blockIdx.y;
    const int tile = blockIdx.x;
    const int h0   = tile * HT;
    const int tid  = threadIdx.x;
    const int lane = tid & 31, warp = tid >> 5;
    const int qid  = lane >> 2, qli = lane & 3;   // quad id / quad lane

    // pool: Ahi = pool[0 : 64*AS), Alo = pool[64*AS : 2*64*AS)  (34.8 KB)
    // tail reuses pool[0 : cnt*DD) for K (max 32 KB)
    __shared__ __align__(16) float pool[2 * NMAX * AS];
    float* Ahi = pool;
    float* Alo = pool + NMAX * AS;
    __shared__ float swr[HT];
    __shared__ float qs[DD];
    __shared__ float lg[NMAX];
    __shared__ float sv[NMAX];
    __shared__ int   s_pos[NMAX];
    __shared__ int   s_wsum[4];
    __shared__ int   s_cnt;
    __shared__ int   s_last;

    // ---- kt=0 raw B loads issued FIRST (depend on nothing; L2 latency
    //      overlaps the scan + gather below) ----
    float braw0[4], braw1[4];
    {
        const size_t rbase = (size_t)(h0 + qli) * DD;
#pragma unroll
        for (int t = 0; t < 4; t++) {
            int col = (warp * 4 + t) * 8 + qid;
            braw0[t] = Wk[rbase + col];
            braw1[t] = Wk[rbase + 4 * DD + col];
        }
    }
    if (tid < HT) swr[tid] = Wr[h0 + tid];

    // ---- mask scan: single pass, 128 threads x 32 elements ----
    {
        const int base = tid * 32;
        const int4* m4 = (const int4*)(mask + b * SS + base);
        int v[32];
#pragma unroll
        for (int q = 0; q < 8; q++) {
            int4 t4 = m4[q];
            v[4*q] = t4.x; v[4*q+1] = t4.y; v[4*q+2] = t4.z; v[4*q+3] = t4.w;
        }
        int c = 0;
#pragma unroll
        for (int j = 0; j < 32; j++) c += (v[j] > 0);
        int x = c;
#pragma unroll
        for (int off = 1; off < 32; off <<= 1) {
            int y = __shfl_up_sync(0xffffffffu, x, off);
            if (lane >= off) x += y;
        }
        if (lane == 31) s_wsum[warp] = x;
        __syncthreads();
        int pre = 0;
#pragma unroll
        for (int w = 0; w < 4; w++) pre += (w < warp) ? s_wsum[w] : 0;
        int r = pre + x - c;
#pragma unroll
        for (int j = 0; j < 32; j++) {
            if (v[j] > 0) { if (r < NMAX) s_pos[r] = base + j; r++; }
        }
        if (tid == 0) {
            int tot = s_wsum[0] + s_wsum[1] + s_wsum[2] + s_wsum[3];
            s_cnt = (tot < NMAX) ? tot : NMAX;
        }
        __syncthreads();
    }
    const int cnt  = s_cnt;
    const int last = cnt - 1;
    const int rmax = (cnt > MROWS) ? cnt : MROWS;

    // ---- gather rows -> smem, split into tf32 hi/lo (zero-pad to MROWS) ----
    for (int i = tid; i < rmax * (HT / 4); i += TPB) {
        int row = i >> 4;            // HT/4 = 16 float4 per row
        int c4  = i & 15;
        float4 v;
        if (row < cnt)
            v = *(const float4*)(hid + ((size_t)b * SS + s_pos[row]) * HH
                                     + h0 + c4 * 4);
        else
            v = make_float4(0.f, 0.f, 0.f, 0.f);
        float f[4] = {v.x, v.y, v.z, v.w};
        int base = row * AS + c4 * 4;
#pragma unroll
        for (int e = 0; e < 4; e++) {
            uint32_t hb2 = f2tf(f[e]);
            float hf = __uint_as_float(hb2);
            uint32_t lb = f2tf(f[e] - hf);
            Ahi[base + e] = hf;
            Alo[base + e] = __uint_as_float(lb);
        }
    }
    __syncthreads();

    // ---- K-projection: tf32 MMA, 3-term split, B software-pipelined ----
    float C[3][4][4];
#pragma unroll
    for (int mt = 0; mt < 3; mt++)
#pragma unroll
        for (int t = 0; t < 4; t++)
#pragma unroll
            for (int e = 0; e < 4; e++) C[mt][t][e] = 0.0f;

#pragma unroll
    for (int kt = 0; kt < 8; kt++) {
        // prefetch kt+1 raw B (in flight during this kt's cvt/LDS/MMA)
        float nb0[4], nb1[4];
        if (kt < 7) {
            const size_t rbase = (size_t)(h0 + (kt + 1) * 8 + qli) * DD;
#pragma unroll
            for (int t = 0; t < 4; t++) {
                int col = (warp * 4 + t) * 8 + qid;
                nb0[t] = Wk[rbase + col];
                nb1[t] = Wk[rbase + 4 * DD + col];
            }
        }
        // convert current raw B -> tf32 hi/lo fragments
        uint32_t bh0[4], bh1[4], bl0[4], bl1[4];
#pragma unroll
        for (int t = 0; t < 4; t++) {
            bh0[t] = f2tf(braw0[t]);
            bl0[t] = f2tf(braw0[t] - __uint_as_float(bh0[t]));
            bh1[t] = f2tf(braw1[t]);
            bl1[t] = f2tf(braw1[t] - __uint_as_float(bh1[t]));
        }
        // A fragments: 3 m-tiles, hi & lo
        uint32_t ah[3][4], al[3][4];
#pragma unroll
        for (int mt = 0; mt < 3; mt++) {
            int base = (mt * 16 + qid) * AS + kt * 8 + qli;
            ah[mt][0] = __float_as_uint(Ahi[base]);
            ah[mt][1] = __float_as_uint(Ahi[base + 8 * AS]);
            ah[mt][2] = __float_as_uint(Ahi[base + 4]);
            ah[mt][3] = __float_as_uint(Ahi[base + 8 * AS + 4]);
            al[mt][0] = __float_as_uint(Alo[base]);
            al[mt][1] = __float_as_uint(Alo[base + 8 * AS]);
            al[mt][2] = __float_as_uint(Alo[base + 4]);
            al[mt][3] = __float_as_uint(Alo[base + 8 * AS + 4]);
        }
#pragma unroll
        for (int mt = 0; mt < 3; mt++)
#pragma unroll
            for (int t = 0; t < 4; t++) {
                MMA(C[mt][t][0], C[mt][t][1], C[mt][t][2], C[mt][t][3],
                    ah[mt][0], ah[mt][1], ah[mt][2], ah[mt][3],
                    bh0[t], bh1[t]);
                MMA(C[mt][t][0], C[mt][t][1], C[mt][t][2], C[mt][t][3],
                    ah[mt][0], ah[mt][1], ah[mt][2], ah[mt][3],
                    bl0[t], bl1[t]);
                MMA(C[mt][t][0], C[mt][t][1], C[mt][t][2], C[mt][t][3],
                    al[mt][0], al[mt][1], al[mt][2], al[mt][3],
                    bh0[t], bh1[t]);
            }
#pragma unroll
        for (int t = 0; t < 4; t++) { braw0[t] = nb0[t]; braw1[t] = nb1[t]; }
    }

    // ---- flush C with v2-RED burst (rows < cnt only) ----
#pragma unroll
    for (int mt = 0; mt < 3; mt++) {
        int r0 = mt * 16 + qid;
#pragma unroll
        for (int t = 0; t < 4; t++) {
            int col = (warp * 4 + t) * 8 + 2 * qli;
            if (r0 < cnt)
                red_v2(&g_K[b][r0][col], C[mt][t][0], C[mt][t][1]);
            if (r0 + 8 < cnt)
                red_v2(&g_K[b][r0 + 8][col], C[mt][t][2], C[mt][t][3]);
        }
    }

    // ---- V: warp handles rows r = warp, warp+4, ... ----
    for (int r = warp; r < cnt; r += 4) {
        float a0 = Ahi[r * AS + lane]      + Alo[r * AS + lane];
        float a1 = Ahi[r * AS + 32 + lane] + Alo[r * AS + 32 + lane];
        float v = a0 * swr[lane] + a1 * swr[lane + 32];
#pragma unroll
        for (int off = 16; off; off >>= 1)
            v += __shfl_down_sync(0xffffffffu, v, off);
        if (lane == 0) red_f32(&g_V[b][r], v);
    }

    // ---- Q: thread d = tid; 4 independent accumulator chains ----
    {
        float aq0 = 0.f, aq1 = 0.f, aq2 = 0.f, aq3 = 0.f;
        const float* ar = &Ahi[last * AS];
        const float* al2 = &Alo[last * AS];
#pragma unroll 4
        for (int h = 0; h < HT; h += 4) {
            float w0 = Wq[(size_t)(h0 + h)     * DD + tid];
            float w1 = Wq[(size_t)(h0 + h + 1) * DD + tid];
            float w2 = Wq[(size_t)(h0 + h + 2) * DD + tid];
            float w3 = Wq[(size_t)(h0 + h + 3) * DD + tid];
            aq0 += (ar[h]     + al2[h])     * w0;
            aq1 += (ar[h + 1] + al2[h + 1]) * w1;
            aq2 += (ar[h + 2] + al2[h + 2]) * w2;
            aq3 += (ar[h + 3] + al2[h + 3]) * w3;
        }
        float aq = (aq0 + aq1) + (aq2 + aq3);
        float pq = __shfl_xor_sync(0xffffffffu, aq, 1);
        if ((tid & 1) == 0) red_v2(&g_Q[b][tid], aq, pq);
    }

    // ---- per-batch arrival: 64th block proceeds to attention ----
    __threadfence();
    __syncthreads();
    if (tid == 0) {
        int old = atomicAdd(&g_arrive[b], 1);
        s_last = (old == ARR_TARGET - 1);
        if (s_last) g_arrive[b] = 0;
    }
    __syncthreads();
    if (!s_last) return;
    __threadfence();                     // acquire: make all REDs visible

    // =================== attention tail (1 block per batch) ================
    {
        float4* b4 = (float4*)pool;
        float4 z = make_float4(0.f, 0.f, 0.f, 0.f);
        int tot = cnt * (DD / 4);
        for (int ii = tid; ii < tot; ii += TPB) {
            int row = ii >> 5, c4 = ii & 31;
            float4 v = *(const float4*)&g_K[b][row][c4 * 4];
            b4[ii] = v;
            *(float4*)&g_K[b][row][c4 * 4] = z;
        }
    }
    if (tid < NMAX) { sv[tid] = g_V[b][tid]; g_V[b][tid] = 0.0f; }

    const float LN_THETA = 9.210340371976184f;   // ln(10000)

    {
        float freq = __expf(-LN_THETA * (float)(2 * (tid >> 1)) * (1.0f / 128.0f));
        float qv = g_Q[b][tid] + bq[tid];
        g_Q[b][tid] = 0.0f;
        float a = (float)last * freq;
        float cq = __cosf(a), sq = __sinf(a);
        float qp = __shfl_xor_sync(0xffffffffu, qv, 1);
        qs[tid] = ((tid & 1) == 0) ? (qv * cq - qp * sq) : (qp * sq + qv * cq);
    }
    __syncthreads();

    float fr[4];
#pragma unroll
    for (int s4 = 0; s4 < 4; s4++) {
        int dd = lane + s4 * 32;
        fr[s4] = __expf(-LN_THETA * (float)(2 * (dd >> 1)) * (1.0f / 128.0f));
    }
    for (int n = warp; n < cnt; n += 4) {
        float dot = 0.0f;
        float nf = (float)n;
#pragma unroll
        for (int s4 = 0; s4 < 4; s4++) {
            int dd = lane + s4 * 32;
            float kv = pool[n * DD + dd] + bk[dd];
            float a = nf * fr[s4];
            float cn = __cosf(a), sn = __sinf(a);
            float kp = __shfl_xor_sync(0xffffffffu, kv, 1);
            float kr = ((dd & 1) == 0) ? (kv * cn - kp * sn) : (kp * sn + kv * cn);
            dot += qs[dd] * kr;
        }
#pragma unroll
        for (int off = 16; off; off >>= 1)
            dot += __shfl_xor_sync(0xffffffffu, dot, off);
        if (lane == 0) lg[n] = dot * 0.08838834764831845f;  // 1/sqrt(128)
    }
    __syncthreads();

    if (warp == 0) {
        const float NEG = -3.0e38f;
        int n0 = lane, n1 = lane + 32;
        bool v0ok = (n0 < cnt), v1ok = (n1 < cnt);
        float l0 = v0ok ? lg[n0] : NEG;
        float l1 = v1ok ? lg[n1] : NEG;
        float mx = fmaxf(l0, l1);
#pragma unroll
        for (int off = 16; off; off >>= 1)
            mx = fmaxf(mx, __shfl_xor_sync(0xffffffffu, mx, off));

        float br0 = br[0];
        float e0 = v0ok ? __expf(l0 - mx) : 0.0f;
        float e1 = v1ok ? __expf(l1 - mx) : 0.0f;
        float vn0 = v0ok ? (sv[n0] + br0) : 0.0f;
        float vp0 = (v0ok && n0 > 0) ? (sv[n0 - 1] + br0) : 0.0f;
        float vn1 = v1ok ? (sv[n1] + br0) : 0.0f;
        float vp1 = v1ok ? (sv[n1 - 1] + br0) : 0.0f;
        float sum = e0 + e1;
        float rew = e0 * (vn0 - vp0) + e1 * (vn1 - vp1);
#pragma unroll
        for (int off = 16; off; off >>= 1) {
            sum += __shfl_xor_sync(0xffffffffu, sum, off);
            rew += __shfl_xor_sync(0xffffffffu, rew, off);
        }
        if (lane == 0) {
            g_rew[b] = rew / sum;
            __threadfence();
            int old2 = atomicAdd(&g_done, 1);
            if (old2 == BB - 1) {
                __threadfence();
                float r[BB];
#pragma unroll
                for (int k = 0; k < BB; k++) r[k] = g_rew[k];
                float loss = 0.0f;
#pragma unroll
                for (int k = 0; k < 4; k++) {
                    float x = r[k] - r[k + 4];
                    loss += (x >= 0.0f) ? log1pf(expf(-x))
                                        : (-x + log1pf(expf(x)));
                }
                loss *= 0.25f;
                if (out_size >= 9) {
                    out[0] = loss;
                    for (int k = 0; k < 8; k++) out[1 + k] = r[k];
                } else if (out_size == 8) {
                    for (int k = 0; k < 8; k++) out[k] = r[k];
                } else {
                    out[0] = loss;
                }
                g_done = 0;
            }
        }
    }
}

// ---------------------------------------------------------------------------
extern "C" void kernel_launch(void* const* d_in, const int* in_sizes, int n_in,
                              void* d_out, int out_size) {
    const float* hid  = (const float*)d_in[0];
    const int*   mask = (const int*)  d_in[1];
    const float* Wq   = (const float*)d_in[2];
    const float* bq   = (const float*)d_in[3];
    const float* Wk   = (const float*)d_in[4];
    const float* bk   = (const float*)d_in[5];
    const float* Wr   = (const float*)d_in[6];
    const float* br   = (const float*)d_in[7];
    float* out = (float*)d_out;

    k_fused<<<dim3(NT, BB), TPB>>>(hid, mask, Wq, bq, Wk, bk, Wr, br,
                                   out, out_size);
}

// round 16
// speedup vs baseline: 1.0359x; 1.0359x over previous
#include <cuda_runtime.h>
#include <math.h>
#include <stdint.h>

#define BB 8
#define SS 4096
#define HH 4096
#define DD 128
#define NMAX 64
#define NT 64            /* k-slices (h tiles of 64) */
#define HT 64
#define TPB 256
#define MROWS 48         /* MMA-covered rows (3 m-tiles of 16) */
#define AS 68            /* padded A row stride (floats) */
#define ARR_TARGET NT

// -------- persistent scratch: zero at load; tail re-zeros each replay ------
__device__ float g_K[BB][NMAX][DD];
__device__ float g_Q[BB][DD];
__device__ float g_V[BB][NMAX];
__device__ float g_rew[BB];
__device__ int   g_arrive[BB];
__device__ int   g_done;

__device__ __forceinline__ void red_f32(float* p, float v) {
    asm volatile("red.global.add.f32 [%0], %1;" :: "l"(p), "f"(v) : "memory");
}
__device__ __forceinline__ void red_v2(float* p, float x, float y) {
    asm volatile("red.global.add.v2.f32 [%0], {%1,%2};"
                 :: "l"(p), "f"(x), "f"(y) : "memory");
}
__device__ __forceinline__ uint32_t f2tf(float f) {
    uint32_t u; asm("cvt.rna.tf32.f32 %0,%1;" : "=r"(u) : "f"(f)); return u;
}

#define MMA(c0,c1,c2,c3,a0,a1,a2,a3,b0,b1)                                 \
    asm volatile("mma.sync.aligned.m16n8k8.row.col.f32.tf32.tf32.f32 "     \
        "{%0,%1,%2,%3},{%4,%5,%6,%7},{%8,%9},{%0,%1,%2,%3};"               \
        : "+f"(c0), "+f"(c1), "+f"(c2), "+f"(c3)                           \
        : "r"(a0), "r"(a1), "r"(a2), "r"(a3), "r"(b0), "r"(b1))

// ---------------------------------------------------------------------------
// ONE fused kernel. grid=(NT, BB), 256 threads (8 warps).
// R14 structure; warp owns 2 n-tiles (was 4) -> 2x eligible warps per SMSP.
// ---------------------------------------------------------------------------
__global__ void __launch_bounds__(TPB)
k_fused(const float* __restrict__ hid,
        const int*   __restrict__ mask,
        const float* __restrict__ Wq,
        const float* __restrict__ bq,
        const float* __restrict__ Wk,
        const float* __restrict__ bk,
        const float* __restrict__ Wr,
        const float* __restrict__ br,
        float* __restrict__ out, int out_size) {
    const int b    = blockIdx.y;
    const int tile = blockIdx.x;
    const int h0   = tile * HT;
    const int tid  = threadIdx.x;
    const int lane = tid & 31, warp = tid >> 5;   // 8 warps
    const int qid  = lane >> 2, qli = lane & 3;   // quad id / quad lane
    const int d    = tid & (DD - 1);
    const int half = tid >> 7;                    // 0/1: h-half for Q

    // pool: Ahi = pool[0 : 64*AS), Alo = pool[64*AS : 2*64*AS)  (34.8 KB)
    // tail reuses pool[0 : cnt*DD) for K (max 32 KB)
    __shared__ __align__(16) float pool[2 * NMAX * AS];
    float* Ahi = pool;
    float* Alo = pool + NMAX * AS;
    __shared__ float swr[HT];
    __shared__ float qs[DD];
    __shared__ float lg[NMAX];
    __shared__ float sv[NMAX];
    __shared__ int   s_pos[NMAX];
    __shared__ int   s_wsum[8];
    __shared__ int   s_cnt;
    __shared__ int   s_last;

    if (tid < HT) swr[tid] = Wr[h0 + tid];

    // ---- mask scan: single pass, 256 threads x 16 elements ----
    {
        const int base = tid * 16;
        const int4* m4 = (const int4*)(mask + b * SS + base);
        int v[16];
#pragma unroll
        for (int q = 0; q < 4; q++) {
            int4 t4 = m4[q];
            v[4*q] = t4.x; v[4*q+1] = t4.y; v[4*q+2] = t4.z; v[4*q+3] = t4.w;
        }
        int c = 0;
#pragma unroll
        for (int j = 0; j < 16; j++) c += (v[j] > 0);
        int x = c;
#pragma unroll
        for (int off = 1; off < 32; off <<= 1) {
            int y = __shfl_up_sync(0xffffffffu, x, off);
            if (lane >= off) x += y;
        }
        if (lane == 31) s_wsum[warp] = x;
        __syncthreads();
        int pre = 0;
#pragma unroll
        for (int w = 0; w < 8; w++) pre += (w < warp) ? s_wsum[w] : 0;
        int r = pre + x - c;
#pragma unroll
        for (int j = 0; j < 16; j++) {
            if (v[j] > 0) { if (r < NMAX) s_pos[r] = base + j; r++; }
        }
        if (tid == 0) {
            int tot = 0;
#pragma unroll
            for (int w = 0; w < 8; w++) tot += s_wsum[w];
            s_cnt = (tot < NMAX) ? tot : NMAX;
        }
        __syncthreads();
    }
    const int cnt  = s_cnt;
    const int last = cnt - 1;
    const int rmax = (cnt > MROWS) ? cnt : MROWS;

    // ---- gather rows -> smem, split into tf32 hi/lo (zero-pad to MROWS) ----
    for (int i = tid; i < rmax * (HT / 4); i += TPB) {
        int row = i >> 4;            // HT/4 = 16 float4 per row
        int c4  = i & 15;
        float4 v;
        if (row < cnt)
            v = *(const float4*)(hid + ((size_t)b * SS + s_pos[row]) * HH
                                     + h0 + c4 * 4);
        else
            v = make_float4(0.f, 0.f, 0.f, 0.f);
        float f[4] = {v.x, v.y, v.z, v.w};
        int base = row * AS + c4 * 4;
#pragma unroll
        for (int e = 0; e < 4; e++) {
            uint32_t hb2 = f2tf(f[e]);
            float hf = __uint_as_float(hb2);
            uint32_t lb = f2tf(f[e] - hf);
            Ahi[base + e] = hf;
            Alo[base + e] = __uint_as_float(lb);
        }
    }
    __syncthreads();

    // ---- V: warp handles rows r = warp, warp+8, ... ----
    for (int r = warp; r < cnt; r += 8) {
        float a0 = Ahi[r * AS + lane]      + Alo[r * AS + lane];
        float a1 = Ahi[r * AS + 32 + lane] + Alo[r * AS + 32 + lane];
        float v = a0 * swr[lane] + a1 * swr[lane + 32];
#pragma unroll
        for (int off = 16; off; off >>= 1)
            v += __shfl_down_sync(0xffffffffu, v, off);
        if (lane == 0) red_f32(&g_V[b][r], v);
    }

    // ---- Q: thread (d, half); each half covers 32 h-values ----
    {
        const int hb = half * (HT / 2);
        float aq0 = 0.f, aq1 = 0.f;
        const float* ar  = &Ahi[last * AS + hb];
        const float* al2 = &Alo[last * AS + hb];
#pragma unroll 8
        for (int h = 0; h < HT / 2; h += 2) {
            float w0 = Wq[(size_t)(h0 + hb + h)     * DD + d];
            float w1 = Wq[(size_t)(h0 + hb + h + 1) * DD + d];
            aq0 += (ar[h]     + al2[h])     * w0;
            aq1 += (ar[h + 1] + al2[h + 1]) * w1;
        }
        float aq = aq0 + aq1;
        float pq = __shfl_xor_sync(0xffffffffu, aq, 1);
        if ((d & 1) == 0) red_v2(&g_Q[b][d], aq, pq);
    }

    // ---- K-projection: tf32 MMA, 3-term split; warp owns 2 n-tiles ----
    float C[3][2][4];
#pragma unroll
    for (int mt = 0; mt < 3; mt++)
#pragma unroll
        for (int t = 0; t < 2; t++)
#pragma unroll
            for (int e = 0; e < 4; e++) C[mt][t][e] = 0.0f;

#pragma unroll 2
    for (int kt = 0; kt < 8; kt++) {
        // B fragments: warp's 2 n-tiles
        uint32_t bh0[2], bh1[2], bl0[2], bl1[2];
#pragma unroll
        for (int t = 0; t < 2; t++) {
            int col = (warp * 2 + t) * 8 + qid;
            size_t r0 = (size_t)(h0 + kt * 8 + qli) * DD + col;
            float bv0 = Wk[r0];
            float bv1 = Wk[r0 + 4 * DD];
            bh0[t] = f2tf(bv0);
            bl0[t] = f2tf(bv0 - __uint_as_float(bh0[t]));
            bh1[t] = f2tf(bv1);
            bl1[t] = f2tf(bv1 - __uint_as_float(bh1[t]));
        }
        // A fragments: 3 m-tiles, hi & lo
        uint32_t ah[3][4], al[3][4];
#pragma unroll
        for (int mt = 0; mt < 3; mt++) {
            int base = (mt * 16 + qid) * AS + kt * 8 + qli;
            ah[mt][0] = __float_as_uint(Ahi[base]);
            ah[mt][1] = __float_as_uint(Ahi[base + 8 * AS]);
            ah[mt][2] = __float_as_uint(Ahi[base + 4]);
            ah[mt][3] = __float_as_uint(Ahi[base + 8 * AS + 4]);
            al[mt][0] = __float_as_uint(Alo[base]);
            al[mt][1] = __float_as_uint(Alo[base + 8 * AS]);
            al[mt][2] = __float_as_uint(Alo[base + 4]);
            al[mt][3] = __float_as_uint(Alo[base + 8 * AS + 4]);
        }
#pragma unroll
        for (int mt = 0; mt < 3; mt++)
#pragma unroll
            for (int t = 0; t < 2; t++) {
                MMA(C[mt][t][0], C[mt][t][1], C[mt][t][2], C[mt][t][3],
                    ah[mt][0], ah[mt][1], ah[mt][2], ah[mt][3],
                    bh0[t], bh1[t]);
                MMA(C[mt][t][0], C[mt][t][1], C[mt][t][2], C[mt][t][3],
                    ah[mt][0], ah[mt][1], ah[mt][2], ah[mt][3],
                    bl0[t], bl1[t]);
                MMA(C[mt][t][0], C[mt][t][1], C[mt][t][2], C[mt][t][3],
                    al[mt][0], al[mt][1], al[mt][2], al[mt][3],
                    bh0[t], bh1[t]);
            }
    }

    // ---- flush C with v2-RED burst (rows < cnt only) ----
#pragma unroll
    for (int mt = 0; mt < 3; mt++) {
        int r0 = mt * 16 + qid;
#pragma unroll
        for (int t = 0; t < 2; t++) {
            int col = (warp * 2 + t) * 8 + 2 * qli;
            if (r0 < cnt)
                red_v2(&g_K[b][r0][col], C[mt][t][0], C[mt][t][1]);
            if (r0 + 8 < cnt)
                red_v2(&g_K[b][r0 + 8][col], C[mt][t][2], C[mt][t][3]);
        }
    }

    // ---- scalar fallback for rows >= MROWS (never taken when cnt<=48) ----
    for (int n = MROWS + half; n < cnt; n += 2) {
        float acc = 0.0f;
        for (int h = 0; h < HT; h++) {
            float a = Ahi[n * AS + h] + Alo[n * AS + h];
            acc += a * Wk[(size_t)(h0 + h) * DD + d];
        }
        red_f32(&g_K[b][n][d], acc);
    }

    // ---- per-batch arrival: 64th block proceeds to attention ----
    __threadfence();
    __syncthreads();
    if (tid == 0) {
        int old = atomicAdd(&g_arrive[b], 1);
        s_last = (old == ARR_TARGET - 1);
        if (s_last) g_arrive[b] = 0;
    }
    __syncthreads();
    if (!s_last) return;
    __threadfence();                     // acquire: make all REDs visible

    // =================== attention tail (1 block per batch) ================
    {
        float4* b4 = (float4*)pool;
        float4 z = make_float4(0.f, 0.f, 0.f, 0.f);
        int tot = cnt * (DD / 4);
        for (int ii = tid; ii < tot; ii += TPB) {
            int row = ii >> 5, c4 = ii & 31;
            float4 v = *(const float4*)&g_K[b][row][c4 * 4];
            b4[ii] = v;
            *(float4*)&g_K[b][row][c4 * 4] = z;
        }
    }
    if (tid < NMAX) { sv[tid] = g_V[b][tid]; g_V[b][tid] = 0.0f; }

    const float LN_THETA = 9.210340371976184f;   // ln(10000)

    if (tid < DD) {
        float freq = __expf(-LN_THETA * (float)(2 * (tid >> 1)) * (1.0f / 128.0f));
        float qv = g_Q[b][tid] + bq[tid];
        g_Q[b][tid] = 0.0f;
        float a = (float)last * freq;
        float cq = __cosf(a), sq = __sinf(a);
        float qp = __shfl_xor_sync(0xffffffffu, qv, 1);
        qs[tid] = ((tid & 1) == 0) ? (qv * cq - qp * sq) : (qp * sq + qv * cq);
    }
    __syncthreads();

    float fr[4];
#pragma unroll
    for (int s4 = 0; s4 < 4; s4++) {
        int dd = lane + s4 * 32;
        fr[s4] = __expf(-LN_THETA * (float)(2 * (dd >> 1)) * (1.0f / 128.0f));
    }
    for (int n = warp; n < cnt; n += 8) {
        float dot = 0.0f;
        float nf = (float)n;
#pragma unroll
        for (int s4 = 0; s4 < 4; s4++) {
            int dd = lane + s4 * 32;
            float kv = pool[n * DD + dd] + bk[dd];
            float a = nf * fr[s4];
            float cn = __cosf(a), sn = __sinf(a);
            float kp = __shfl_xor_sync(0xffffffffu, kv, 1);
            float kr = ((dd & 1) == 0) ? (kv * cn - kp * sn) : (kp * sn + kv * cn);
            dot += qs[dd] * kr;
        }
#pragma unroll
        for (int off = 16; off; off >>= 1)
            dot += __shfl_xor_sync(0xffffffffu, dot, off);
        if (lane == 0) lg[n] = dot * 0.08838834764831845f;  // 1/sqrt(128)
    }
    __syncthreads();

    if (warp == 0) {
        const float NEG = -3.0e38f;
        int n0 = lane, n1 = lane + 32;
        bool v0ok = (n0 < cnt), v1ok = (n1 < cnt);
        float l0 = v0ok ? lg[n0] : NEG;
        float l1 = v1ok ? lg[n1] : NEG;
        float mx = fmaxf(l0, l1);
#pragma unroll
        for (int off = 16; off; off >>= 1)
            mx = fmaxf(mx, __shfl_xor_sync(0xffffffffu, mx, off));

        float br0 = br[0];
        float e0 = v0ok ? __expf(l0 - mx) : 0.0f;
        float e1 = v1ok ? __expf(l1 - mx) : 0.0f;
        float vn0 = v0ok ? (sv[n0] + br0) : 0.0f;
        float vp0 = (v0ok && n0 > 0) ? (sv[n0 - 1] + br0) : 0.0f;
        float vn1 = v1ok ? (sv[n1] + br0) : 0.0f;
        float vp1 = v1ok ? (sv[n1 - 1] + br0) : 0.0f;
        float sum = e0 + e1;
        float rew = e0 * (vn0 - vp0) + e1 * (vn1 - vp1);
#pragma unroll
        for (int off = 16; off; off >>= 1) {
            sum += __shfl_xor_sync(0xffffffffu, sum, off);
            rew += __shfl_xor_sync(0xffffffffu, rew, off);
        }
        if (lane == 0) {
            g_rew[b] = rew / sum;
            __threadfence();
            int old2 = atomicAdd(&g_done, 1);
            if (old2 == BB - 1) {
                __threadfence();
                float r[BB];
#pragma unroll
                for (int k = 0; k < BB; k++) r[k] = g_rew[k];
                float loss = 0.0f;
#pragma unroll
                for (int k = 0; k < 4; k++) {
                    float x = r[k] - r[k + 4];
                    loss += (x >= 0.0f) ? log1pf(expf(-x))
                                        : (-x + log1pf(expf(x)));
                }
                loss *= 0.25f;
                if (out_size >= 9) {
                    out[0] = loss;
                    for (int k = 0; k < 8; k++) out[1 + k] = r[k];
                } else if (out_size == 8) {
                    for (int k = 0; k < 8; k++) out[k] = r[k];
                } else {
                    out[0] = loss;
                }
                g_done = 0;
            }
        }
    }
}

// ---------------------------------------------------------------------------
extern "C" void kernel_launch(void* const* d_in, const int* in_sizes, int n_in,
                              void* d_out, int out_size) {
    const float* hid  = (const float*)d_in[0];
    const int*   mask = (const int*)  d_in[1];
    const float* Wq   = (const float*)d_in[2];
    const float* bq   = (const float*)d_in[3];
    const float* Wk   = (const float*)d_in[4];
    const float* bk   = (const float*)d_in[5];
    const float* Wr   = (const float*)d_in[6];
    const float* br   = (const float*)d_in[7];
    float* out = (float*)d_out;

    k_fused<<<dim3(NT, BB), TPB>>>(hid, mask, Wq, bq, Wk, bk, Wr, br,
                                   out, out_size);
}